// round 7
// baseline (speedup 1.0000x reference)
#include <cuda_runtime.h>
#include <cuda_bf16.h>
#include <cstdint>

// Problem constants
#define NTOK   4096
#define DMODEL 1024
#define DHID   16384
#define TOPK   64

// -------- device scratch (no allocations allowed) --------
__device__ float g_z[(size_t)NTOK * DHID];          // 256 MB dense activations
__device__ int   g_si[NTOK * TOPK];
__device__ float g_sv[NTOK * TOPK];

// ============================================================
// Encode: z = relu(x @ W_enc + b_enc)
// fp32 SGEMM using packed fma.rn.f32x2 (Blackwell FFMA2)
// Tiles: BM=128, BN=128, BK=16; 256 threads; 8x8 per thread.
// Accumulation is strictly sequential in k (single rounded FMA
// per k per output) -> noise vs truth ~2e-6 absolute.
// ============================================================
#define BM 128
#define BN 128
#define BK 16

__global__ __launch_bounds__(256, 2)
void encode_kernel(const float* __restrict__ x,
                   const float* __restrict__ W,
                   const float* __restrict__ bias)
{
    __shared__ __align__(16) float As[BK][BM];       // 8 KB  (k-major, transposed A)
    __shared__ __align__(16) float Bs[BK][2 * BN];   // 16 KB (duplicated pairs [b,b])

    const int tid = threadIdx.x;
    const int tx  = tid & 15;          // 0..15  -> column group
    const int ty  = tid >> 4;          // 0..15  -> row group (8 rows each)
    const int m0  = blockIdx.y * BM;
    const int n0  = blockIdx.x * BN;

    unsigned long long acc[4][8];      // 4 row-pairs x 8 cols, packed f32x2
#pragma unroll
    for (int i = 0; i < 4; ++i)
#pragma unroll
        for (int j = 0; j < 8; ++j) acc[i][j] = 0ULL;

    for (int k0 = 0; k0 < DMODEL; k0 += BK) {
        // ---- load A tile: x[m0+row][k0 + 4*fc .. +3] ----
#pragma unroll
        for (int it = 0; it < 2; ++it) {
            int idx = tid + 256 * it;        // 0..511
            int row = idx >> 2;              // 0..127
            int fc  = idx & 3;               // 0..3
            float4 v = *(const float4*)&x[(size_t)(m0 + row) * DMODEL + k0 + 4 * fc];
            As[4 * fc + 0][row] = v.x;
            As[4 * fc + 1][row] = v.y;
            As[4 * fc + 2][row] = v.z;
            As[4 * fc + 3][row] = v.w;
        }
        // ---- load B tile duplicated: Bs[kk][2j]=Bs[kk][2j+1]=W[k0+kk][n0+j] ----
#pragma unroll
        for (int it = 0; it < 2; ++it) {
            int idx = tid + 256 * it;        // 0..511
            int kk  = idx >> 5;              // 0..15
            int f4  = idx & 31;              // 0..31
            float4 v = *(const float4*)&W[(size_t)(k0 + kk) * DHID + n0 + 4 * f4];
            float4 d0 = make_float4(v.x, v.x, v.y, v.y);
            float4 d1 = make_float4(v.z, v.z, v.w, v.w);
            *(float4*)&Bs[kk][8 * f4 + 0] = d0;
            *(float4*)&Bs[kk][8 * f4 + 4] = d1;
        }
        __syncthreads();

#pragma unroll
        for (int kk = 0; kk < BK; ++kk) {
            // A: 8 consecutive rows -> 4 natural f32x2 pairs
            ulonglong2 a01 = *(const ulonglong2*)&As[kk][ty * 8];
            ulonglong2 a23 = *(const ulonglong2*)&As[kk][ty * 8 + 4];
            unsigned long long a[4] = { a01.x, a01.y, a23.x, a23.y };
#pragma unroll
            for (int jj = 0; jj < 8; ++jj) {
                // duplicated pair [b,b] for column n0 + tx + 16*jj (conflict-free LDS.64)
                unsigned long long bb =
                    *(const unsigned long long*)&Bs[kk][2 * (tx + 16 * jj)];
#pragma unroll
                for (int i2 = 0; i2 < 4; ++i2) {
                    asm("fma.rn.f32x2 %0, %1, %2, %0;"
                        : "+l"(acc[i2][jj]) : "l"(a[i2]), "l"(bb));
                }
            }
        }
        __syncthreads();
    }

    // ---- epilogue: + bias, relu, store z ----
#pragma unroll
    for (int jj = 0; jj < 8; ++jj) {
        int col = n0 + tx + 16 * jj;
        float bv = bias[col];
#pragma unroll
        for (int i2 = 0; i2 < 4; ++i2) {
            unsigned long long p = acc[i2][jj];
            float lo = __uint_as_float((unsigned)(p & 0xffffffffu));
            float hi = __uint_as_float((unsigned)(p >> 32));
            int row = m0 + ty * 8 + 2 * i2;
            g_z[(size_t)row * DHID + col]       = fmaxf(lo + bv, 0.0f);
            g_z[(size_t)(row + 1) * DHID + col] = fmaxf(hi + bv, 0.0f);
        }
    }
}

// ============================================================
// Top-64 per row, boundary-exact:
//  1) 4-round radix select on float bit patterns -> v64 (fp32).
//  2) z > v64+EPS : definitely selected.
//     |z - v64| <= EPS : boundary band (usually 1 member).
//  3) If band larger than remaining slots, rescore the band
//     members with an fp64 dot product (== true value to 1e-13)
//     and pick by (true value desc, index asc). This makes the
//     selected SET equal to the true top-64 set, immune to fp32
//     accumulation-order noise (ours ~2e-6 << EPS).
//  Output sorted by index (deterministic across replays).
// ============================================================
#define BAND_EPS 1e-4f
#define BAND_CAP 64

__global__ void topk_kernel(const float* __restrict__ x,
                            const float* __restrict__ W)
{
    __shared__ unsigned int hist[256];
    __shared__ unsigned int s_prefix, s_need, s_nout, s_nb;
    __shared__ int    s_bi[BAND_CAP];
    __shared__ float  s_bv[BAND_CAP];
    __shared__ double s_bs[BAND_CAP];
    __shared__ double s_red[8];
    __shared__ int    s_oi[TOPK];
    __shared__ float  s_ov[TOPK];

    const int row = blockIdx.x;
    const int tid = threadIdx.x;
    const float* __restrict__ zr = g_z + (size_t)row * DHID;

    if (tid == 0) { s_prefix = 0u; s_need = TOPK; }
    __syncthreads();

    // ---- 4 radix rounds -> exact fp32 key of rank-64 value ----
    for (int rr = 0; rr < 4; ++rr) {
        hist[tid] = 0u;
        __syncthreads();
        unsigned int pfx = s_prefix;
        int shift = 24 - 8 * rr;
        for (int i = tid; i < DHID; i += 256) {
            unsigned int key = __float_as_uint(zr[i]);
            bool ok = (rr == 0) || ((key >> (shift + 8)) == pfx);
            if (ok) atomicAdd(&hist[(key >> shift) & 255u], 1u);
        }
        __syncthreads();
        if (tid == 0) {
            unsigned int need = s_need, cum = 0;
            int b;
            for (b = 255; b >= 0; --b) {
                unsigned int c = hist[b];
                if (cum + c >= need) break;
                cum += c;
            }
            if (b < 0) b = 0;
            s_need   = need - cum;
            s_prefix = (pfx << 8) | (unsigned int)b;
        }
        __syncthreads();
    }

    const float v64 = __uint_as_float(s_prefix);
    const float bhi = v64 + BAND_EPS;
    const float blo = v64 - BAND_EPS;

    if (tid == 0) { s_nout = 0u; s_nb = 0u; }
    __syncthreads();

    // ---- emission: definite vs boundary band ----
    for (int i = tid; i < DHID; i += 256) {
        float z = zr[i];
        if (z > bhi) {
            unsigned int p = atomicAdd(&s_nout, 1u);
            s_oi[p] = i;
            s_ov[p] = z;
        } else if (z >= blo) {
            unsigned int q = atomicAdd(&s_nb, 1u);
            if (q < BAND_CAP) { s_bi[q] = i; s_bv[q] = z; }
        }
    }
    __syncthreads();

    const int nb    = (int)min(s_nb, (unsigned)BAND_CAP);
    const int base  = (int)s_nout;
    const int slots = TOPK - base;

    if (nb == slots) {
        // uncontested boundary: take the whole band
        if (tid < nb) { s_oi[base + tid] = s_bi[tid]; s_ov[base + tid] = s_bv[tid]; }
    } else {
        // contested: fp64 rescore band members (true values)
        for (int b = 0; b < nb; ++b) {
            const int f = s_bi[b];
            double part = 0.0;
            for (int k = tid; k < DMODEL; k += 256)
                part += (double)x[(size_t)row * DMODEL + k] *
                        (double)W[(size_t)k * DHID + f];
#pragma unroll
            for (int o = 16; o > 0; o >>= 1)
                part += __shfl_down_sync(0xffffffffu, part, o);
            if ((tid & 31) == 0) s_red[tid >> 5] = part;
            __syncthreads();
            if (tid == 0) {
                double s = 0.0;
#pragma unroll
                for (int w = 0; w < 8; ++w) s += s_red[w];
                s_bs[b] = s;
            }
            __syncthreads();
        }
        // pick top `slots` by (true value desc, index asc)
        if (tid < nb) {
            double mv = s_bs[tid];
            int    mi = s_bi[tid];
            int rank = 0;
            for (int j = 0; j < nb; ++j)
                if (s_bs[j] > mv || (s_bs[j] == mv && s_bi[j] < mi)) ++rank;
            if (rank < slots) {
                unsigned int p = atomicAdd(&s_nout, 1u);
                s_oi[p] = mi;
                s_ov[p] = s_bv[tid];      // emit the fp32 z (matches ref to ~2e-6)
            }
        }
    }
    __syncthreads();

    // ---- sort the 64 entries by index -> deterministic output order ----
    if (tid < TOPK) {
        int my = s_oi[tid];
        unsigned int rank = 0;
#pragma unroll
        for (int j = 0; j < TOPK; ++j) rank += (s_oi[j] < my) ? 1u : 0u;
        g_si[row * TOPK + rank] = my;
        g_sv[row * TOPK + rank] = s_ov[tid];
    }
}

// ============================================================
// Decode: y[row] = b_dec + sum_f sel_val * W_dec[sel_idx, :]
// One block per row, 256 threads x 4 cols (float4). W_dec is
// 64 MB -> L2 resident; ~1 GB of L2 gather traffic total.
// ============================================================
__global__ __launch_bounds__(256)
void decode_kernel(const float* __restrict__ Wd,
                   const float* __restrict__ bd,
                   float* __restrict__ y)
{
    __shared__ int   si[TOPK];
    __shared__ float sv[TOPK];
    const int row = blockIdx.x;
    const int tid = threadIdx.x;

    if (tid < TOPK) {
        si[tid] = g_si[row * TOPK + tid];
        sv[tid] = g_sv[row * TOPK + tid];
    }
    __syncthreads();

    float4 acc = *(const float4*)&bd[4 * tid];
#pragma unroll 8
    for (int f = 0; f < TOPK; ++f) {
        float v = sv[f];
        const float4 w = *(const float4*)&Wd[(size_t)si[f] * DMODEL + 4 * tid];
        acc.x = fmaf(v, w.x, acc.x);
        acc.y = fmaf(v, w.y, acc.y);
        acc.z = fmaf(v, w.z, acc.z);
        acc.w = fmaf(v, w.w, acc.w);
    }
    *(float4*)&y[(size_t)row * DMODEL + 4 * tid] = acc;
}

// ============================================================
extern "C" void kernel_launch(void* const* d_in, const int* in_sizes, int n_in,
                              void* d_out, int out_size)
{
    const float* x     = (const float*)d_in[0];   // [4096,1024]
    const float* W_enc = (const float*)d_in[1];   // [1024,16384]
    const float* b_enc = (const float*)d_in[2];   // [16384]
    const float* W_dec = (const float*)d_in[3];   // [16384,1024]
    const float* b_dec = (const float*)d_in[4];   // [1024]
    float* y = (float*)d_out;                     // [4096,1024]

    dim3 eg(DHID / BN, NTOK / BM);                // (128, 32)
    encode_kernel<<<eg, 256>>>(x, W_enc, b_enc);
    topk_kernel<<<NTOK, 256>>>(x, W_enc);
    decode_kernel<<<NTOK, 256>>>(W_dec, b_dec, y);
}

// round 10
// speedup vs baseline: 2.7260x; 2.7260x over previous
#include <cuda_runtime.h>
#include <cuda_bf16.h>
#include <cstdint>

// Problem constants
#define NTOK   4096
#define DMODEL 1024
#define DHID   16384
#define TOPK   64

// -------- device scratch (no allocations allowed) --------
__device__ float         g_z [(size_t)NTOK * DHID];     // 256 MB approx activations
__device__ int           g_si[NTOK * TOPK];
__device__ float         g_sv[NTOK * TOPK];
__device__ __nv_bfloat16 g_xh[(size_t)NTOK * DMODEL];   // bf16(x)
__device__ __nv_bfloat16 g_wh[(size_t)DHID * DMODEL];   // bf16(W_enc^T) [n][k]
__device__ float         g_wt[(size_t)DHID * DMODEL];   // fp32 W_enc^T  [n][k]

// ============================================================
// PTX helpers (all legal on plain compute_103: no 'a' features)
// ============================================================
__device__ __forceinline__ uint32_t smem_u32(const void* p) {
    uint32_t a;
    asm("{ .reg .u64 t; cvta.to.shared.u64 t, %1; cvt.u32.u64 %0, t; }"
        : "=r"(a) : "l"(p));
    return a;
}
__device__ __forceinline__ void cp16(uint32_t saddr, const void* gaddr) {
    asm volatile("cp.async.ca.shared.global [%0], [%1], 16;" :: "r"(saddr), "l"(gaddr));
}
#define CP_COMMIT() asm volatile("cp.async.commit_group;" ::: "memory")
#define CP_WAIT1()  asm volatile("cp.async.wait_group 1;" ::: "memory")

#define LDSM_X4(r0, r1, r2, r3, addr) \
    asm volatile("ldmatrix.sync.aligned.m8n8.x4.shared.b16 {%0,%1,%2,%3}, [%4];" \
                 : "=r"(r0), "=r"(r1), "=r"(r2), "=r"(r3) : "r"(addr))

__device__ __forceinline__ void mma16816(float* c,
                                         uint32_t a0, uint32_t a1, uint32_t a2, uint32_t a3,
                                         uint32_t b0, uint32_t b1)
{
    asm volatile(
        "mma.sync.aligned.m16n8k16.row.col.f32.bf16.bf16.f32 "
        "{%0,%1,%2,%3}, {%4,%5,%6,%7}, {%8,%9}, {%0,%1,%2,%3};"
        : "+f"(c[0]), "+f"(c[1]), "+f"(c[2]), "+f"(c[3])
        : "r"(a0), "r"(a1), "r"(a2), "r"(a3), "r"(b0), "r"(b1));
}

// ============================================================
// Conversions
// ============================================================
__global__ void convert_x_kernel(const float* __restrict__ x)
{
    int i = blockIdx.x * 256 + threadIdx.x;
    g_xh[i] = __float2bfloat16(x[i]);
}

// W_enc [k=1024][n=16384]  ->  g_wt/g_wh [n][k] (transposed)
__global__ __launch_bounds__(256)
void convert_w_kernel(const float* __restrict__ W)
{
    __shared__ float t[32][33];
    const int n0 = blockIdx.x * 32;
    const int k0 = blockIdx.y * 32;
    const int tx = threadIdx.x & 31;
    const int ty = threadIdx.x >> 5;          // 0..7
#pragma unroll
    for (int r = ty; r < 32; r += 8)
        t[r][tx] = W[(size_t)(k0 + r) * DHID + n0 + tx];
    __syncthreads();
#pragma unroll
    for (int r = ty; r < 32; r += 8) {
        float v = t[tx][r];                   // = W[k0+tx][n0+r]
        size_t o = (size_t)(n0 + r) * DMODEL + k0 + tx;
        g_wt[o] = v;
        g_wh[o] = __float2bfloat16(v);
    }
}

// ============================================================
// Encode (approx): g_z = relu(bf16(x) @ bf16(W) + b) via mma.sync
// CTA 128x128, K-chunk 64, 2-stage cp.async pipeline.
// 8 warps (2x4), warp tile 64x32, m16n8k16 bf16->fp32.
// smem rows padded to 144B: conflict-free ldmatrix phases.
// ============================================================
#define ROWB   144                              // 64 bf16 + 8 pad = 144 bytes
#define TILEB  (128 * ROWB)                     // 18432 B per operand tile
#define STAGEB (2 * TILEB)                      // A + B
#define ENC_SMEM (2 * STAGEB)                   // 73728 B

__global__ __launch_bounds__(256, 2)
void encode_mma_kernel(const float* __restrict__ bias)
{
    extern __shared__ __align__(16) char dsm[];
    const uint32_t sbase = smem_u32(dsm);
    const int tid  = threadIdx.x;
    const int lane = tid & 31;
    const int wid  = tid >> 5;
    const int wm   = wid >> 2;                  // 0..1 -> m offset 64*wm
    const int wn   = wid & 3;                   // 0..3 -> n offset 32*wn
    const int m0   = blockIdx.x * 128;
    const int n0   = blockIdx.y * 128;

    const __nv_bfloat16* gA = g_xh + (size_t)m0 * DMODEL;
    const __nv_bfloat16* gB = g_wh + (size_t)n0 * DMODEL;

    float acc[2][4][4];                         // [mt(2 of 4 m16 per wm? no: 4)]...
    // warp tile 64x32 -> 4 m16-tiles x 4 n8-tiles
    float accr[4][4][4];
#pragma unroll
    for (int i = 0; i < 4; ++i)
#pragma unroll
        for (int j = 0; j < 4; ++j)
#pragma unroll
            for (int q = 0; q < 4; ++q) accr[i][j][q] = 0.0f;
    (void)acc;

    // ---- stage loader: 2048 x 16B chunks, 8 per thread ----
    auto load_stage = [&](int st, int c) {
        const int k0 = c * 64;
        const uint32_t sA = sbase + st * STAGEB;
        const uint32_t sB = sA + TILEB;
#pragma unroll
        for (int i = 0; i < 4; ++i) {
            int id = tid + 256 * i;             // 0..1023
            int r  = id >> 3;                   // row 0..127
            int cc = id & 7;                    // 16B chunk 0..7
            cp16(sA + r * ROWB + cc * 16, gA + (size_t)r * DMODEL + k0 + cc * 8);
            cp16(sB + r * ROWB + cc * 16, gB + (size_t)r * DMODEL + k0 + cc * 8);
        }
    };

    load_stage(0, 0);
    CP_COMMIT();

    for (int c = 0; c < DMODEL / 64; ++c) {
        if (c + 1 < DMODEL / 64) load_stage((c + 1) & 1, c + 1);
        CP_COMMIT();
        CP_WAIT1();                             // chunk c's group complete
        __syncthreads();

        const uint32_t sA = sbase + (c & 1) * STAGEB;
        const uint32_t sB = sA + TILEB;
        // per-lane ldmatrix address components
        const uint32_t aRow = (uint32_t)(wm * 64 + (lane & 15));
        const uint32_t aCol = (uint32_t)((lane >> 4) << 4);
        const uint32_t bRow = (uint32_t)(wn * 32 + (lane & 7) + ((lane >> 4) << 3));
        const uint32_t bCol = (uint32_t)(((lane >> 3) & 1) << 4);

#pragma unroll
        for (int kt = 0; kt < 4; ++kt) {
            uint32_t a[4][4];
#pragma unroll
            for (int mt = 0; mt < 4; ++mt)
                LDSM_X4(a[mt][0], a[mt][1], a[mt][2], a[mt][3],
                        sA + (aRow + mt * 16) * ROWB + kt * 32 + aCol);
            uint32_t b[2][4];
#pragma unroll
            for (int np = 0; np < 2; ++np)
                LDSM_X4(b[np][0], b[np][1], b[np][2], b[np][3],
                        sB + (bRow + np * 16) * ROWB + kt * 32 + bCol);
#pragma unroll
            for (int mt = 0; mt < 4; ++mt)
#pragma unroll
                for (int nt = 0; nt < 4; ++nt)
                    mma16816(accr[mt][nt],
                             a[mt][0], a[mt][1], a[mt][2], a[mt][3],
                             b[nt >> 1][(nt & 1) * 2], b[nt >> 1][(nt & 1) * 2 + 1]);
        }
        __syncthreads();                        // buffer (c&1) free for reuse at c+2
    }

    // ---- epilogue: bias + relu, direct global stores (8B/lane/row) ----
#pragma unroll
    for (int nt = 0; nt < 4; ++nt) {
        const int col = n0 + wn * 32 + nt * 8 + 2 * (lane & 3);
        const float bv0 = bias[col];
        const float bv1 = bias[col + 1];
#pragma unroll
        for (int mt = 0; mt < 4; ++mt) {
            const int row = m0 + wm * 64 + mt * 16 + (lane >> 2);
            float2 o0, o1;
            o0.x = fmaxf(accr[mt][nt][0] + bv0, 0.0f);
            o0.y = fmaxf(accr[mt][nt][1] + bv1, 0.0f);
            o1.x = fmaxf(accr[mt][nt][2] + bv0, 0.0f);
            o1.y = fmaxf(accr[mt][nt][3] + bv1, 0.0f);
            *(float2*)&g_z[(size_t)row * DHID + col]       = o0;
            *(float2*)&g_z[(size_t)(row + 8) * DHID + col] = o1;
        }
    }
}

// ============================================================
// Top-64 per row on approx z̃, boundary-exact selection:
//  radix-select -> ṽ64; band = ±BAND_EPS (10 sigma of bf16-GEMM
//  noise). definite ⊆ true-set; true-set ⊆ definite ∪ band.
//  Contested band resolved by fp64 rescore (true values, reads
//  fp32 W^T coalesced). Selected SET == true top-64.
//  Writes indices only (values recomputed exactly afterwards).
// ============================================================
#define BAND_EPS 0.024f
#define BAND_CAP 192

__global__ void topk_kernel(const float* __restrict__ x)
{
    __shared__ unsigned int hist[256];
    __shared__ unsigned int s_prefix, s_need, s_nout, s_nb;
    __shared__ int    s_bi[BAND_CAP];
    __shared__ double s_bs[BAND_CAP];
    __shared__ double s_red[8];
    __shared__ int    s_oi[TOPK];

    const int row = blockIdx.x;
    const int tid = threadIdx.x;
    const float* __restrict__ zr = g_z + (size_t)row * DHID;

    if (tid == 0) { s_prefix = 0u; s_need = TOPK; }
    __syncthreads();

    for (int rr = 0; rr < 4; ++rr) {
        hist[tid] = 0u;
        __syncthreads();
        unsigned int pfx = s_prefix;
        int shift = 24 - 8 * rr;
        for (int i = tid; i < DHID; i += 256) {
            unsigned int key = __float_as_uint(zr[i]);
            bool ok = (rr == 0) || ((key >> (shift + 8)) == pfx);
            if (ok) atomicAdd(&hist[(key >> shift) & 255u], 1u);
        }
        __syncthreads();
        if (tid == 0) {
            unsigned int need = s_need, cum = 0;
            int b;
            for (b = 255; b >= 0; --b) {
                unsigned int c = hist[b];
                if (cum + c >= need) break;
                cum += c;
            }
            if (b < 0) b = 0;
            s_need   = need - cum;
            s_prefix = (pfx << 8) | (unsigned int)b;
        }
        __syncthreads();
    }

    const float v64 = __uint_as_float(s_prefix);
    const float bhi = v64 + BAND_EPS;
    const float blo = v64 - BAND_EPS;

    if (tid == 0) { s_nout = 0u; s_nb = 0u; }
    __syncthreads();

    for (int i = tid; i < DHID; i += 256) {
        float z = zr[i];
        if (z > bhi) {
            unsigned int p = atomicAdd(&s_nout, 1u);
            s_oi[p] = i;
        } else if (z >= blo) {
            unsigned int q = atomicAdd(&s_nb, 1u);
            if (q < BAND_CAP) s_bi[q] = i;
        }
    }
    __syncthreads();

    const int nb    = (int)min(s_nb, (unsigned)BAND_CAP);
    const int base  = (int)s_nout;
    const int slots = TOPK - base;

    if (nb == slots) {
        if (tid < nb) s_oi[base + tid] = s_bi[tid];
    } else {
        // fp64 rescore of band members (true values); coalesced g_wt rows
        for (int b = 0; b < nb; ++b) {
            const int f = s_bi[b];
            const float* wr = g_wt + (size_t)f * DMODEL;
            double part = 0.0;
            for (int k = tid; k < DMODEL; k += 256)
                part += (double)x[(size_t)row * DMODEL + k] * (double)wr[k];
#pragma unroll
            for (int o = 16; o > 0; o >>= 1)
                part += __shfl_down_sync(0xffffffffu, part, o);
            if ((tid & 31) == 0) s_red[tid >> 5] = part;
            __syncthreads();
            if (tid == 0) {
                double s = 0.0;
#pragma unroll
                for (int w = 0; w < 8; ++w) s += s_red[w];
                s_bs[b] = s;
            }
            __syncthreads();
        }
        if (tid < nb) {
            double mv = s_bs[tid];
            int    mi = s_bi[tid];
            int rank = 0;
            for (int j = 0; j < nb; ++j)
                if (s_bs[j] > mv || (s_bs[j] == mv && s_bi[j] < mi)) ++rank;
            if (rank < slots) {
                unsigned int p = atomicAdd(&s_nout, 1u);
                s_oi[p] = mi;
            }
        }
    }
    __syncthreads();

    // sort selected indices ascending -> deterministic
    if (tid < TOPK) {
        int my = s_oi[tid];
        unsigned int rank = 0;
#pragma unroll
        for (int j = 0; j < TOPK; ++j) rank += (s_oi[j] < my) ? 1u : 0u;
        g_si[row * TOPK + rank] = my;
    }
}

// ============================================================
// Exact fp32 recompute of the 64 selected z values per row:
// g_sv[row][j] = relu( dot_fp32(x[row], W^T[f]) + b_enc[f] )
// ============================================================
__global__ __launch_bounds__(256)
void exact_kernel(const float* __restrict__ x, const float* __restrict__ be)
{
    __shared__ float sx[DMODEL];
    const int row  = blockIdx.x;
    const int tid  = threadIdx.x;
    const int w    = tid >> 5;
    const int lane = tid & 31;

    for (int i = tid; i < DMODEL; i += 256)
        sx[i] = x[(size_t)row * DMODEL + i];
    __syncthreads();
    const float4* sx4 = (const float4*)sx;

    for (int j = w; j < TOPK; j += 8) {
        const int f = g_si[row * TOPK + j];
        const float4* wr = (const float4*)(g_wt + (size_t)f * DMODEL);
        float s = 0.0f;
#pragma unroll
        for (int k4 = lane; k4 < DMODEL / 4; k4 += 32) {
            float4 xv = sx4[k4];
            float4 wv = wr[k4];
            s += xv.x * wv.x + xv.y * wv.y + xv.z * wv.z + xv.w * wv.w;
        }
#pragma unroll
        for (int o = 16; o > 0; o >>= 1)
            s += __shfl_down_sync(0xffffffffu, s, o);
        if (lane == 0)
            g_sv[row * TOPK + j] = fmaxf(s + be[f], 0.0f);
    }
}

// ============================================================
// Decode: y[row] = b_dec + sum_f sel_val * W_dec[sel_idx, :]
// ============================================================
__global__ __launch_bounds__(256)
void decode_kernel(const float* __restrict__ Wd,
                   const float* __restrict__ bd,
                   float* __restrict__ y)
{
    __shared__ int   si[TOPK];
    __shared__ float sv[TOPK];
    const int row = blockIdx.x;
    const int tid = threadIdx.x;

    if (tid < TOPK) {
        si[tid] = g_si[row * TOPK + tid];
        sv[tid] = g_sv[row * TOPK + tid];
    }
    __syncthreads();

    float4 acc = *(const float4*)&bd[4 * tid];
#pragma unroll 8
    for (int f = 0; f < TOPK; ++f) {
        float v = sv[f];
        const float4 w = *(const float4*)&Wd[(size_t)si[f] * DMODEL + 4 * tid];
        acc.x = fmaf(v, w.x, acc.x);
        acc.y = fmaf(v, w.y, acc.y);
        acc.z = fmaf(v, w.z, acc.z);
        acc.w = fmaf(v, w.w, acc.w);
    }
    *(float4*)&y[(size_t)row * DMODEL + 4 * tid] = acc;
}

// ============================================================
extern "C" void kernel_launch(void* const* d_in, const int* in_sizes, int n_in,
                              void* d_out, int out_size)
{
    const float* x     = (const float*)d_in[0];   // [4096,1024]
    const float* W_enc = (const float*)d_in[1];   // [1024,16384]
    const float* b_enc = (const float*)d_in[2];   // [16384]
    const float* W_dec = (const float*)d_in[3];   // [16384,1024]
    const float* b_dec = (const float*)d_in[4];   // [1024]
    float* y = (float*)d_out;                     // [4096,1024]

    cudaFuncSetAttribute(encode_mma_kernel,
                         cudaFuncAttributeMaxDynamicSharedMemorySize, ENC_SMEM);

    convert_x_kernel<<<NTOK * DMODEL / 256, 256>>>(x);
    convert_w_kernel<<<dim3(DHID / 32, DMODEL / 32), 256>>>(W_enc);
    // grid.x = m tiles (fast) so co-resident CTAs share B (n) slices in L2
    encode_mma_kernel<<<dim3(NTOK / 128, DHID / 128), 256, ENC_SMEM>>>(b_enc);
    topk_kernel<<<NTOK, 256>>>(x);
    exact_kernel<<<NTOK, 256>>>(x, b_enc);
    decode_kernel<<<NTOK, 256>>>(W_dec, b_dec, y);
}